// round 13
// baseline (speedup 1.0000x reference)
#include <cuda_runtime.h>
#include <cuda_bf16.h>

// Fast Walsh-Hadamard transform, 16384 rows x 1024 fp32.
// y[row] = FWHT(x[row]) / 32, emitted as interleaved (real, 0) pairs.
//
// Top two stages (strides 256, 512) folded into the load:
//   y[256k + i] = FWHT_256(z_k)[i],  z_k[i] = sum_q (-1)^popc(k&q) x[256q+i]
// FOUR warps per row (quarter k = warp % 4), all in the same block so the
// 4x row re-read hits L1 (8KB block working set). Each warp: 16 coalesced
// LDG.64, 24 FMA combine, then a warp-local FWHT_256 with 8 values/thread:
//   stride 1        -> register butterfly (b pair)
//   strides 2..32   -> 5 shfl.xor stages (40 shuffles total)
//   strides 64,128  -> register butterflies over j
// Low registers -> high occupancy; large grid (8192); short serial chain.
// Stores: 4 coalesced STG.128 per warp, zero-imag folded in.

#define DIMN 1024

__device__ __forceinline__ void bf(float &x, float &y) {
    float s = x + y;
    y = x - y;
    x = s;
}

__global__ void __launch_bounds__(256, 6)
fwht_kernel(const float2* __restrict__ xin, float4* __restrict__ yout, int nrows)
{
    const int l   = threadIdx.x & 31;
    const int w   = threadIdx.x >> 5;
    const int row = blockIdx.x * 2 + (w >> 2);
    const int k   = w & 3;                    // quarter index
    if (row >= nrows) return;

    const float s1 = (k & 1) ? -1.0f : 1.0f;  // sign for q bit 0 (stride 256)
    const float s2 = (k & 2) ? -1.0f : 1.0f;  // sign for q bit 1 (stride 512)

    // float2 index l + 32j in quarter q covers elements 2l + 64j + {0,1}
    const float2* in = xin + (size_t)row * (DIMN / 2) + l;

    float a[4], b[4];      // a: elements 2l+64j, b: 2l+1+64j of z_k
    {
        // batch 1: quarters 0,1  (8 loads in flight)
        float2 p0[4], p1[4];
        #pragma unroll
        for (int j = 0; j < 4; j++) p0[j] = in[32 * j];
        #pragma unroll
        for (int j = 0; j < 4; j++) p1[j] = in[128 + 32 * j];

        float u[4], ub[4];
        #pragma unroll
        for (int j = 0; j < 4; j++) {
            u[j]  = fmaf(s1, p1[j].x, p0[j].x);
            ub[j] = fmaf(s1, p1[j].y, p0[j].y);
        }

        // batch 2: quarters 2,3
        #pragma unroll
        for (int j = 0; j < 4; j++) p0[j] = in[256 + 32 * j];
        #pragma unroll
        for (int j = 0; j < 4; j++) p1[j] = in[384 + 32 * j];

        #pragma unroll
        for (int j = 0; j < 4; j++) {
            float v  = fmaf(s1, p1[j].x, p0[j].x);
            float vb = fmaf(s1, p1[j].y, p0[j].y);
            a[j] = fmaf(s2, v,  u[j]);
            b[j] = fmaf(s2, vb, ub[j]);
        }
    }

    // ---- stride 1 (register, b-pair) ----
    #pragma unroll
    for (int j = 0; j < 4; j++) bf(a[j], b[j]);

    // ---- strides 2,4,8,16,32 via shfl.xor on lane bits ----
    #pragma unroll
    for (int d = 1; d <= 16; d <<= 1) {
        const bool up = (l & d) != 0;
        #pragma unroll
        for (int j = 0; j < 4; j++) {
            float oa = __shfl_xor_sync(0xffffffffu, a[j], d);
            float ob = __shfl_xor_sync(0xffffffffu, b[j], d);
            a[j] = up ? (oa - a[j]) : (a[j] + oa);
            b[j] = up ? (ob - b[j]) : (b[j] + ob);
        }
    }

    // ---- strides 64,128: butterflies over j bits ----
    bf(a[0], a[1]); bf(a[2], a[3]); bf(b[0], b[1]); bf(b[2], b[3]);
    bf(a[0], a[2]); bf(a[1], a[3]); bf(b[0], b[2]); bf(b[1], b[3]);

    // ---- scaled, interleaved (real, 0) stores: 4 coalesced STG.128 ----
    // element 256k + 2l + 64j -> out float4 index 128k + l + 32j
    const float sc = 0.03125f;   // 1/sqrt(1024)
    float4* out = yout + (size_t)row * (2 * DIMN / 4) + 128 * k + l;
    #pragma unroll
    for (int j = 0; j < 4; j++) {
        __stcs(out + 32 * j, make_float4(a[j] * sc, 0.0f, b[j] * sc, 0.0f));
    }
}

extern "C" void kernel_launch(void* const* d_in, const int* in_sizes, int n_in,
                              void* d_out, int out_size)
{
    const float* x = (const float*)d_in[0];   // [B, S, 1024] fp32
    // d_in[1] is H; unused — the transform is computed directly.
    float* out = (float*)d_out;               // [B, S, 1024, 2] fp32

    const int nrows = in_sizes[0] / DIMN;     // 16384
    const int grid  = (nrows + 1) / 2;        // 2 rows per 256-thread block

    fwht_kernel<<<grid, 256>>>((const float2*)x, (float4*)out, nrows);
}

// round 14
// speedup vs baseline: 1.0094x; 1.0094x over previous
#include <cuda_runtime.h>
#include <cuda_bf16.h>

// Fast Walsh-Hadamard transform, 16384 rows x 1024 fp32.
// y[row] = FWHT(x[row]) / 32, emitted as interleaved (real, 0) pairs.
//
// Top two stages (strides 256, 512) folded into the load:
//   y[256k + i] = FWHT_256(z_k)[i],  z_k[i] = sum_q (-1)^popc(k&q) x[256q+i]
// FOUR warps per row (quarter k = warp % 4), all in the same block so the
// 4x row re-read hits L1 (8KB block working set). Each warp: 16 coalesced
// LDG.64, 24 FMA combine, then a warp-local FWHT_256 with 8 values/thread:
//   stride 1        -> register butterfly (b pair)
//   strides 2..32   -> 5 shfl.xor stages (40 shuffles total)
//   strides 64,128  -> register butterflies over j
// Low registers -> high occupancy; large grid (8192); short serial chain.
// Stores: 4 coalesced STG.128 per warp, zero-imag folded in.

#define DIMN 1024

__device__ __forceinline__ void bf(float &x, float &y) {
    float s = x + y;
    y = x - y;
    x = s;
}

__global__ void __launch_bounds__(256, 6)
fwht_kernel(const float2* __restrict__ xin, float4* __restrict__ yout, int nrows)
{
    const int l   = threadIdx.x & 31;
    const int w   = threadIdx.x >> 5;
    const int row = blockIdx.x * 2 + (w >> 2);
    const int k   = w & 3;                    // quarter index
    if (row >= nrows) return;

    const float s1 = (k & 1) ? -1.0f : 1.0f;  // sign for q bit 0 (stride 256)
    const float s2 = (k & 2) ? -1.0f : 1.0f;  // sign for q bit 1 (stride 512)

    // float2 index l + 32j in quarter q covers elements 2l + 64j + {0,1}
    const float2* in = xin + (size_t)row * (DIMN / 2) + l;

    float a[4], b[4];      // a: elements 2l+64j, b: 2l+1+64j of z_k
    {
        // batch 1: quarters 0,1  (8 loads in flight)
        float2 p0[4], p1[4];
        #pragma unroll
        for (int j = 0; j < 4; j++) p0[j] = in[32 * j];
        #pragma unroll
        for (int j = 0; j < 4; j++) p1[j] = in[128 + 32 * j];

        float u[4], ub[4];
        #pragma unroll
        for (int j = 0; j < 4; j++) {
            u[j]  = fmaf(s1, p1[j].x, p0[j].x);
            ub[j] = fmaf(s1, p1[j].y, p0[j].y);
        }

        // batch 2: quarters 2,3
        #pragma unroll
        for (int j = 0; j < 4; j++) p0[j] = in[256 + 32 * j];
        #pragma unroll
        for (int j = 0; j < 4; j++) p1[j] = in[384 + 32 * j];

        #pragma unroll
        for (int j = 0; j < 4; j++) {
            float v  = fmaf(s1, p1[j].x, p0[j].x);
            float vb = fmaf(s1, p1[j].y, p0[j].y);
            a[j] = fmaf(s2, v,  u[j]);
            b[j] = fmaf(s2, vb, ub[j]);
        }
    }

    // ---- stride 1 (register, b-pair) ----
    #pragma unroll
    for (int j = 0; j < 4; j++) bf(a[j], b[j]);

    // ---- strides 2,4,8,16,32 via shfl.xor on lane bits ----
    #pragma unroll
    for (int d = 1; d <= 16; d <<= 1) {
        const bool up = (l & d) != 0;
        #pragma unroll
        for (int j = 0; j < 4; j++) {
            float oa = __shfl_xor_sync(0xffffffffu, a[j], d);
            float ob = __shfl_xor_sync(0xffffffffu, b[j], d);
            a[j] = up ? (oa - a[j]) : (a[j] + oa);
            b[j] = up ? (ob - b[j]) : (b[j] + ob);
        }
    }

    // ---- strides 64,128: butterflies over j bits ----
    bf(a[0], a[1]); bf(a[2], a[3]); bf(b[0], b[1]); bf(b[2], b[3]);
    bf(a[0], a[2]); bf(a[1], a[3]); bf(b[0], b[2]); bf(b[1], b[3]);

    // ---- scaled, interleaved (real, 0) stores: 4 coalesced STG.128 ----
    // element 256k + 2l + 64j -> out float4 index 128k + l + 32j
    const float sc = 0.03125f;   // 1/sqrt(1024)
    float4* out = yout + (size_t)row * (2 * DIMN / 4) + 128 * k + l;
    #pragma unroll
    for (int j = 0; j < 4; j++) {
        __stcs(out + 32 * j, make_float4(a[j] * sc, 0.0f, b[j] * sc, 0.0f));
    }
}

extern "C" void kernel_launch(void* const* d_in, const int* in_sizes, int n_in,
                              void* d_out, int out_size)
{
    const float* x = (const float*)d_in[0];   // [B, S, 1024] fp32
    // d_in[1] is H; unused — the transform is computed directly.
    float* out = (float*)d_out;               // [B, S, 1024, 2] fp32

    const int nrows = in_sizes[0] / DIMN;     // 16384
    const int grid  = (nrows + 1) / 2;        // 2 rows per 256-thread block

    fwht_kernel<<<grid, 256>>>((const float2*)x, (float4*)out, nrows);
}

// round 16
// speedup vs baseline: 1.1233x; 1.1128x over previous
#include <cuda_runtime.h>
#include <cuda_bf16.h>

// Fast Walsh-Hadamard transform, 16384 rows x 1024 fp32.
// y[row] = FWHT(x[row]) / 32, emitted as interleaved (real, 0) pairs.
//
// One warp per row, 32 values per thread (leanest MIO ops/element of all
// variants: 16 LDG.64 + 80 SHFL + 16 STG.128 per thread-row), with the
// occupancy cap fixed: 128-thread blocks, __launch_bounds__(128, 9) forces
// regs <= 56 so 36 warps/SM fit (vs R3's 32-warp cap / 40% achieved).
// Loads via __ldg (input measured L2-resident across replays); stores are
// evict-first (__stcs) so the 134MB write stream passes through L2.
//
// Lane l owns elements {2l + b + 64j : b in {0,1}, j in 0..15}:
//   stride 1            -> register butterfly (b pair)
//   strides 2..32       -> 5 shfl.xor stages (lane bits)
//   strides 64..512     -> register butterflies over j bits
// No shared memory, no barriers.

#define DIMN 1024
#define WPB  4          // warps (=rows) per block -> 128 threads

__device__ __forceinline__ void bf(float &x, float &y) {
    float s = x + y;
    y = x - y;
    x = s;
}

__global__ void __launch_bounds__(32 * WPB, 9)
fwht_kernel(const float2* __restrict__ xin, float4* __restrict__ yout, int nrows)
{
    const int l   = threadIdx.x & 31;
    const int w   = threadIdx.x >> 5;
    const int row = blockIdx.x * WPB + w;
    if (row >= nrows) return;

    float a[16], b[16];

    // ---- 16 independent coalesced LDG.64, front-batched ----
    const float2* in = xin + (size_t)row * (DIMN / 2) + l;
    #pragma unroll
    for (int j = 0; j < 16; j++) {
        float2 p = __ldg(in + 32 * j);
        a[j] = p.x;            // element 2l   + 64j
        b[j] = p.y;            // element 2l+1 + 64j
    }

    // ---- stride 1 (register, b-pair) ----
    #pragma unroll
    for (int j = 0; j < 16; j++) bf(a[j], b[j]);

    // ---- strides 2,4,8,16,32 via shfl.xor on lane bits ----
    #pragma unroll
    for (int d = 1; d <= 16; d <<= 1) {
        const bool up = (l & d) != 0;
        #pragma unroll
        for (int j = 0; j < 16; j++) {
            float oa = __shfl_xor_sync(0xffffffffu, a[j], d);
            float ob = __shfl_xor_sync(0xffffffffu, b[j], d);
            a[j] = up ? (oa - a[j]) : (a[j] + oa);
            b[j] = up ? (ob - b[j]) : (b[j] + ob);
        }
    }

    // ---- strides 64,128,256,512: butterflies over j bits ----
    #pragma unroll
    for (int s = 1; s <= 8; s <<= 1) {
        #pragma unroll
        for (int j = 0; j < 16; j++) {
            if ((j & s) == 0) {
                bf(a[j], a[j + s]);
                bf(b[j], b[j + s]);
            }
        }
    }

    // ---- scaled, interleaved (real, 0) stores; 16 coalesced STG.128 ----
    const float sc = 0.03125f;   // 1/sqrt(1024)
    float4* out = yout + (size_t)row * (2 * DIMN / 4) + l;
    #pragma unroll
    for (int j = 0; j < 16; j++) {
        __stcs(out + 32 * j, make_float4(a[j] * sc, 0.0f, b[j] * sc, 0.0f));
    }
}

extern "C" void kernel_launch(void* const* d_in, const int* in_sizes, int n_in,
                              void* d_out, int out_size)
{
    const float* x = (const float*)d_in[0];   // [B, S, 1024] fp32
    // d_in[1] is H; unused — the transform is computed directly.
    float* out = (float*)d_out;               // [B, S, 1024, 2] fp32

    const int nrows = in_sizes[0] / DIMN;     // 16384
    const int grid  = (nrows + WPB - 1) / WPB;

    fwht_kernel<<<grid, 32 * WPB>>>((const float2*)x, (float4*)out, nrows);
}